// round 1
// baseline (speedup 1.0000x reference)
#include <cuda_runtime.h>
#include <math.h>

// ---------------- problem constants ----------------
#define BB        64
#define NN        128
#define FLAT      8192          // B*N
#define H_DIM     128
#define NODE_S    64
#define NODE_V    32
#define OUT_S     32
#define OUT_V     16
#define OUT_DIM   80            // OUT_S + 3*OUT_V
#define RBF_N     16
#define ZEMB      32
#define HIDN      128
#define LATN      256
#define EDIM      16
#define NEE       512
#define EATT_N    4096
#define WN        4608          // 64*32 + 32*32 + 64*16 + 32*16
#define GATE_IN_N 273
#define WIN_N     49
#define CUTOFF_F  5.0f
#define NORM_F    0.10206207261596575f   // 1/sqrt(96)
#define SQRT3_F   1.7320508075688772f
#define NACT_MAX  4096
#define ROWS3     32768         // B * NE

// ---------------- scratch (static device memory; no allocation) ----------------
__device__ int   g_winner[FLAT];
__device__ int   g_active[FLAT];
__device__ int   g_count;
__device__ float g_hid   [NACT_MAX * HIDN];
__device__ float g_mul   [NACT_MAX];          // gate * env * norm
__device__ float g_u     [NACT_MAX * 3];
__device__ float g_tpw   [NACT_MAX * WN];     // 75.5 MB
__device__ float g_ve    [FLAT * OUT_DIM];
__device__ float g_vabs  [BB * OUT_DIM];
__device__ float g_scales[NEE * 48];
__device__ float g_inv   [ROWS3 * 48];
__device__ float g_x1    [ROWS3 * 128];
__device__ float g_x2    [ROWS3 * 128];

__device__ __forceinline__ float siluf(float x) { return x / (1.0f + expf(-x)); }
__device__ __forceinline__ float sigmoidf_(float x) { return 1.0f / (1.0f + expf(-x)); }

// ---------------- k_init: reset scratch that must be re-derived each replay ----
__global__ void k_init() {
    int i = blockIdx.x * blockDim.x + threadIdx.x;
    if (i < FLAT) g_winner[i] = -1;
    if (i == 0)   g_count = 0;
    if (i < FLAT * OUT_DIM) g_ve[i] = 0.0f;
}

// ---------------- k_scatter: last-write-wins == max edge index ----------------
__global__ void k_scatter(const int* __restrict__ att_dst) {
    int e = blockIdx.x * blockDim.x + threadIdx.x;
    if (e < EATT_N) atomicMax(&g_winner[att_dst[e]], e);
}

// ---------------- k_compact -----------------------------------------------------
__global__ void k_compact() {
    int i = blockIdx.x * blockDim.x + threadIdx.x;
    if (i < FLAT && g_winner[i] >= 0) {
        int p = atomicAdd(&g_count, 1);
        g_active[p] = i;
    }
}

// ---------------- k_stage1: per-active-node small MLPs (8 nodes / block) -------
#define NPB 8
__global__ void __launch_bounds__(128)
k_stage1(const float* __restrict__ h,
         const int*   __restrict__ z,
         const int*   __restrict__ absorber_index,
         const float* __restrict__ att_dist,
         const float* __restrict__ att_vec,
         const float* __restrict__ w_zemb,
         const float* __restrict__ w1_rad, const float* __restrict__ b1_rad,
         const float* __restrict__ wg1,    const float* __restrict__ bg1,
         const float* __restrict__ wg2,    const float* __restrict__ bg2)
{
    __shared__ float win[NPB][WIN_N];
    __shared__ float gin[NPB][GATE_IN_N];
    __shared__ float senv[NPB];
    __shared__ float red[128];

    const int tid   = threadIdx.x;
    const int count = g_count;
    const int p0    = blockIdx.x * NPB;
    if (p0 >= count) return;

    const float width    = CUTOFF_F / 15.0f;
    const float invwidth = 15.0f / CUTOFF_F;

    // ---- fill smem inputs for up to 8 nodes ----
    for (int s = 0; s < NPB; s++) {
        int pos = p0 + s;
        if (pos >= count) {
            // zero this slot so the accumulate loops stay finite
            if (tid < WIN_N) win[s][tid] = 0.0f;
            gin[s][tid] = 0.0f; gin[s][128 + tid] = 0.0f;
            if (tid < 16) gin[s][256 + tid] = 0.0f;
            if (tid == 0) { gin[s][272] = 0.0f; senv[s] = 0.0f; }
            continue;
        }
        int node = g_active[pos];
        int b = node >> 7, n = node & 127;
        int e = g_winner[node];
        float d = att_dist[e];
        int absb = absorber_index[b];
        float isabs = (n == absb) ? 1.0f : 0.0f;

        if (tid < ZEMB)       win[s][tid] = w_zemb[z[node] * ZEMB + tid];
        else if (tid == ZEMB) win[s][ZEMB] = isabs;
        else if (tid < WIN_N) {
            int k = tid - 33;
            float t = (d - (float)k * width) * invwidth;
            win[s][tid] = expf(-0.5f * t * t);
        }
        gin[s][tid]       = h[(b * NN + absb) * H_DIM + tid];
        gin[s][128 + tid] = h[node * H_DIM + tid];
        if (tid < 16) {
            float t = (d - (float)tid * width) * invwidth;
            gin[s][256 + tid] = expf(-0.5f * t * t);
        }
        if (tid == 0) {
            gin[s][272] = isabs;
            senv[s] = (d < CUTOFF_F) ? 0.5f * (cospif(d / CUTOFF_F) + 1.0f) : 0.0f;
        }
        if (tid < 3) {
            float u = att_vec[e * 3 + tid] / fmaxf(d, 1e-8f);
            g_u[pos * 3 + tid] = u;
        }
    }
    __syncthreads();

    // ---- radial MLP layer 1: win(49) -> hid(128) for 8 nodes ----
    float acc_h[NPB];
#pragma unroll
    for (int s = 0; s < NPB; s++) acc_h[s] = 0.0f;
    for (int k = 0; k < WIN_N; k++) {
        float w = w1_rad[k * HIDN + tid];
#pragma unroll
        for (int s = 0; s < NPB; s++) acc_h[s] += win[s][k] * w;
    }
    // ---- gate MLP layer 1: gin(273) -> 128 for 8 nodes ----
    float acc_g[NPB];
#pragma unroll
    for (int s = 0; s < NPB; s++) acc_g[s] = 0.0f;
    for (int k = 0; k < GATE_IN_N; k++) {
        float w = wg1[k * HIDN + tid];
#pragma unroll
        for (int s = 0; s < NPB; s++) acc_g[s] += gin[s][k] * w;
    }

    float b1v  = b1_rad[tid];
    float bg1v = bg1[tid];
    float wg2v = wg2[tid];
    float bg2v = bg2[0];

    for (int s = 0; s < NPB; s++) {
        int pos = p0 + s;
        bool act = (pos < count);
        if (act) g_hid[pos * HIDN + tid] = siluf(acc_h[s] + b1v);

        red[tid] = act ? siluf(acc_g[s] + bg1v) * wg2v : 0.0f;
        __syncthreads();
        for (int off = 64; off > 0; off >>= 1) {
            if (tid < off) red[tid] += red[tid + off];
            __syncthreads();
        }
        if (act && tid == 0)
            g_mul[pos] = sigmoidf_(red[0] + bg2v) * senv[s] * NORM_F;
        __syncthreads();
    }
}

// ---------------- generic tiled SGEMM: C = act(A@W + bias) ----------------------
// BM=BN=64, BK=16, 256 threads, 4x4 per-thread tile. M%64==0, N%64==0, K%16==0.
__global__ void __launch_bounds__(256)
k_gemm(const float* __restrict__ A, const float* __restrict__ W,
       const float* __restrict__ bias, float* __restrict__ C,
       int M, int N, int K, int act)
{
    __shared__ __align__(16) float As[16][68];
    __shared__ __align__(16) float Ws[16][64];

    const int tid = threadIdx.x;
    const int tx = tid & 15, ty = tid >> 4;
    const int n0 = blockIdx.x * 64, m0 = blockIdx.y * 64;

    const int arow = tid >> 2, ac4 = tid & 3;   // A: 64 rows x 16 cols (float4)
    const int wrow = tid >> 4, wc4 = tid & 15;  // W: 16 rows x 64 cols (float4)

    float acc[4][4];
#pragma unroll
    for (int i = 0; i < 4; i++)
#pragma unroll
        for (int j = 0; j < 4; j++) acc[i][j] = 0.0f;

    for (int k0 = 0; k0 < K; k0 += 16) {
        float4 av = *reinterpret_cast<const float4*>(A + (size_t)(m0 + arow) * K + k0 + ac4 * 4);
        As[ac4 * 4 + 0][arow] = av.x;
        As[ac4 * 4 + 1][arow] = av.y;
        As[ac4 * 4 + 2][arow] = av.z;
        As[ac4 * 4 + 3][arow] = av.w;
        *reinterpret_cast<float4*>(&Ws[wrow][wc4 * 4]) =
            *reinterpret_cast<const float4*>(W + (size_t)(k0 + wrow) * N + n0 + wc4 * 4);
        __syncthreads();
#pragma unroll
        for (int k = 0; k < 16; k++) {
            float4 a = *reinterpret_cast<const float4*>(&As[k][ty * 4]);
            float4 b = *reinterpret_cast<const float4*>(&Ws[k][tx * 4]);
            float ar[4] = {a.x, a.y, a.z, a.w};
            float br[4] = {b.x, b.y, b.z, b.w};
#pragma unroll
            for (int i = 0; i < 4; i++)
#pragma unroll
                for (int j = 0; j < 4; j++) acc[i][j] += ar[i] * br[j];
        }
        __syncthreads();
    }

    float4 bb = *reinterpret_cast<const float4*>(bias + n0 + tx * 4);
    float bv[4] = {bb.x, bb.y, bb.z, bb.w};
#pragma unroll
    for (int i = 0; i < 4; i++) {
        float4 c;
        float cv[4];
#pragma unroll
        for (int j = 0; j < 4; j++) {
            float v = acc[i][j] + bv[j];
            if (act) v = siluf(v);
            cv[j] = v;
        }
        c.x = cv[0]; c.y = cv[1]; c.z = cv[2]; c.w = cv[3];
        *reinterpret_cast<float4*>(C + (size_t)(m0 + ty * 4 + i) * N + n0 + tx * 4) = c;
    }
}

// ---------------- k_contract: tpw(4608) x node tensors -> ve(80) ----------------
__global__ void __launch_bounds__(128)
k_contract(const float* __restrict__ h_full)
{
    __shared__ float s1[NODE_S];
    __shared__ float v1s[NODE_V * 3];
    __shared__ float bvi[NODE_V];
    __shared__ float uu[3];

    const int pos = blockIdx.x;
    if (pos >= g_count) return;
    const int tid = threadIdx.x;
    const int node = g_active[pos];
    const float* hf = h_full + (size_t)node * 160;

    if (tid < NODE_S) s1[tid] = hf[tid];
    if (tid < NODE_V * 3) v1s[tid] = hf[NODE_S + tid];
    if (tid < 3) uu[tid] = g_u[pos * 3 + tid];
    __syncthreads();
    if (tid < NODE_V)
        bvi[tid] = v1s[3 * tid] * uu[0] + v1s[3 * tid + 1] * uu[1] + v1s[3 * tid + 2] * uu[2];
    __syncthreads();

    const float* tp = g_tpw + (size_t)pos * WN;
    const float mul = g_mul[pos];

    if (tid < OUT_S) {
        int o = tid;
        float acc = 0.0f;
#pragma unroll 8
        for (int i = 0; i < NODE_S; i++) acc += s1[i] * tp[i * OUT_S + o];
#pragma unroll 8
        for (int i = 0; i < NODE_V; i++) acc += bvi[i] * tp[2048 + i * OUT_S + o];
        g_ve[(size_t)node * OUT_DIM + o] = acc * mul;
    }
    if (tid >= 64 && tid < 112) {
        int t = tid - 64;
        int o = t & 15, c = t >> 4;      // o<16, c<3
        float sc = 0.0f, sd = 0.0f;
#pragma unroll 8
        for (int i = 0; i < NODE_S; i++) sc += s1[i] * tp[3072 + i * OUT_V + o];
#pragma unroll 8
        for (int i = 0; i < NODE_V; i++) sd += v1s[3 * i + c] * tp[4096 + i * OUT_V + o];
        float yv = SQRT3_F * uu[c];
        g_ve[(size_t)node * OUT_DIM + OUT_S + o * 3 + c] = (sc * yv + sd) * mul;
    }
}

// ---------------- k_vabs: deterministic per-batch reduce ------------------------
__global__ void k_vabs() {
    int b = blockIdx.x, t = threadIdx.x;
    if (t >= OUT_DIM) return;
    float acc = 0.0f;
    for (int n = 0; n < NN; n++)
        acc += g_ve[(size_t)(b * NN + n) * OUT_DIM + t];
    g_vabs[b * OUT_DIM + t] = acc;
}

// ---------------- k_scales: tiny per-edge-type MLP ------------------------------
__global__ void __launch_bounds__(128)
k_scales(const float* __restrict__ e_feat,
         const float* __restrict__ we1, const float* __restrict__ be1,
         const float* __restrict__ we2, const float* __restrict__ be2)
{
    __shared__ float hid[HIDN];
    int e = blockIdx.x, tid = threadIdx.x;
    float acc = be1[tid];
    for (int k = 0; k < EDIM; k++) acc += e_feat[e * EDIM + k] * we1[k * HIDN + tid];
    hid[tid] = siluf(acc);
    __syncthreads();
    if (tid < 48) {
        float s = be2[tid];
        for (int k = 0; k < HIDN; k++) s += hid[k] * we2[k * 48 + tid];
        g_scales[e * 48 + tid] = s;
    }
}

// ---------------- k_inv: build invariants (B*NE rows x 48) ----------------------
__global__ void __launch_bounds__(192)
k_inv()
{
    int row = blockIdx.x * 4 + threadIdx.x / 48;
    int j = threadIdx.x % 48;
    if (row >= ROWS3) return;
    int b = row >> 9, e = row & 511;
    float v;
    if (j < OUT_S) {
        v = g_vabs[b * OUT_DIM + j] * g_scales[e * 48 + j];
    } else {
        int o = j - OUT_S;
        float s = g_scales[e * 48 + OUT_S + o];
        float x0 = g_vabs[b * OUT_DIM + OUT_S + o * 3 + 0] * s;
        float x1 = g_vabs[b * OUT_DIM + OUT_S + o * 3 + 1] * s;
        float x2 = g_vabs[b * OUT_DIM + OUT_S + o * 3 + 2] * s;
        v = sqrtf(x0 * x0 + x1 * x1 + x2 * x2 + 1e-12f);
    }
    g_inv[(size_t)row * 48 + j] = v;
}

// ---------------- launch ---------------------------------------------------------
extern "C" void kernel_launch(void* const* d_in, const int* in_sizes, int n_in,
                              void* d_out, int out_size)
{
    const float* h        = (const float*)d_in[0];
    const float* h_full   = (const float*)d_in[1];
    const int*   z        = (const int*)  d_in[2];
    // d_in[3] = mask (unused)
    const float* e_feat   = (const float*)d_in[4];
    const int*   abs_idx  = (const int*)  d_in[5];
    const int*   att_dst  = (const int*)  d_in[6];
    const float* att_dist = (const float*)d_in[7];
    const float* att_vec  = (const float*)d_in[8];
    const float* w_zemb   = (const float*)d_in[9];
    const float* w1_rad   = (const float*)d_in[10];
    const float* b1_rad   = (const float*)d_in[11];
    const float* w2_rad   = (const float*)d_in[12];
    const float* b2_rad   = (const float*)d_in[13];
    const float* wg1      = (const float*)d_in[14];
    const float* bg1      = (const float*)d_in[15];
    const float* wg2      = (const float*)d_in[16];
    const float* bg2      = (const float*)d_in[17];
    const float* we1      = (const float*)d_in[18];
    const float* be1      = (const float*)d_in[19];
    const float* we2      = (const float*)d_in[20];
    const float* be2      = (const float*)d_in[21];
    const float* wo1      = (const float*)d_in[22];
    const float* bo1      = (const float*)d_in[23];
    const float* wo2      = (const float*)d_in[24];
    const float* bo2      = (const float*)d_in[25];
    const float* wo3      = (const float*)d_in[26];
    const float* bo3      = (const float*)d_in[27];
    float* out = (float*)d_out;

    float* d_hid = nullptr, *d_tpw = nullptr, *d_invp = nullptr,
         * d_x1 = nullptr, *d_x2 = nullptr;
    cudaGetSymbolAddress((void**)&d_hid,  g_hid);
    cudaGetSymbolAddress((void**)&d_tpw,  g_tpw);
    cudaGetSymbolAddress((void**)&d_invp, g_inv);
    cudaGetSymbolAddress((void**)&d_x1,   g_x1);
    cudaGetSymbolAddress((void**)&d_x2,   g_x2);

    k_init<<<(FLAT * OUT_DIM + 255) / 256, 256>>>();
    k_scatter<<<(EATT_N + 255) / 256, 256>>>(att_dst);
    k_compact<<<(FLAT + 255) / 256, 256>>>();
    k_stage1<<<NACT_MAX / NPB, 128>>>(h, z, abs_idx, att_dist, att_vec, w_zemb,
                                      w1_rad, b1_rad, wg1, bg1, wg2, bg2);
    // tpw = hid @ w2_rad + b2  (4096 x 4608, K=128)
    k_gemm<<<dim3(WN / 64, NACT_MAX / 64), 256>>>(d_hid, w2_rad, b2_rad, d_tpw,
                                                  NACT_MAX, WN, HIDN, 0);
    k_contract<<<NACT_MAX, 128>>>(h_full);
    k_vabs<<<BB, 128>>>();
    k_scales<<<NEE, 128>>>(e_feat, we1, be1, we2, be2);
    k_inv<<<ROWS3 / 4, 192>>>();
    // x1 = silu(inv @ wo1 + bo1)
    k_gemm<<<dim3(128 / 64, ROWS3 / 64), 256>>>(d_invp, wo1, bo1, d_x1, ROWS3, 128, 48, 1);
    // x2 = silu(x1 @ wo2 + bo2)
    k_gemm<<<dim3(128 / 64, ROWS3 / 64), 256>>>(d_x1, wo2, bo2, d_x2, ROWS3, 128, 128, 1);
    // out = x2 @ wo3 + bo3
    k_gemm<<<dim3(256 / 64, ROWS3 / 64), 256>>>(d_x2, wo3, bo3, out, ROWS3, 256, 128, 0);
}

// round 2
// speedup vs baseline: 1.2006x; 1.2006x over previous
#include <cuda_runtime.h>
#include <math.h>

// ---------------- problem constants ----------------
#define BB        64
#define NN        128
#define FLAT      8192          // B*N
#define H_DIM     128
#define NODE_S    64
#define NODE_V    32
#define OUT_S     32
#define OUT_V     16
#define OUT_DIM   80            // OUT_S + 3*OUT_V
#define HIDN      128
#define NEE       512
#define EATT_N    4096
#define WN        4608
#define CUTOFF_F  5.0f
#define NORM_F    0.10206207261596575f   // 1/sqrt(96)
#define SQRT3_F   1.7320508075688772f
#define NACT_MAX  4096
#define ROWS3     32768         // B * NE
#define KWIN      64            // padded 49
#define KGIN      288           // padded 273

// ---------------- scratch (static device memory) ----------------
__device__ int   g_winner[FLAT];
__device__ int   g_active[FLAT];
__device__ int   g_count;
__device__ float g_win   [NACT_MAX * KWIN];
__device__ float g_gin   [NACT_MAX * KGIN];
__device__ float g_ghid  [NACT_MAX * HIDN];
__device__ float g_env   [NACT_MAX];
__device__ float g_wg1p  [KGIN * HIDN];
__device__ float g_w1p   [KWIN * HIDN];
__device__ float g_hid   [NACT_MAX * HIDN];
__device__ float g_mul   [NACT_MAX];
__device__ float g_u     [NACT_MAX * 3];
__device__ float g_tpw   [NACT_MAX * WN];     // 75.5 MB
__device__ float g_ve    [FLAT * OUT_DIM];
__device__ float g_vabs  [BB * OUT_DIM];
__device__ float g_scales[NEE * 48];
__device__ float g_inv   [ROWS3 * 48];
__device__ float g_x1    [ROWS3 * 128];
__device__ float g_x2    [ROWS3 * 128];

__device__ __forceinline__ float siluf(float x) { return x / (1.0f + expf(-x)); }
__device__ __forceinline__ float sigmoidf_(float x) { return 1.0f / (1.0f + expf(-x)); }

// ---------------- k_init ----------------
__global__ void k_init() {
    int i = blockIdx.x * blockDim.x + threadIdx.x;
    if (i < FLAT) g_winner[i] = -1;
    if (i == 0)   g_count = 0;
    if (i < FLAT * OUT_DIM) g_ve[i] = 0.0f;
}

// ---------------- k_scatter: last-write-wins == max edge index ----------------
__global__ void k_scatter(const int* __restrict__ att_dst) {
    int e = blockIdx.x * blockDim.x + threadIdx.x;
    if (e < EATT_N) atomicMax(&g_winner[att_dst[e]], e);
}

__global__ void k_compact() {
    int i = blockIdx.x * blockDim.x + threadIdx.x;
    if (i < FLAT && g_winner[i] >= 0) {
        int p = atomicAdd(&g_count, 1);
        g_active[p] = i;
    }
}

// ---------------- k_padw: zero-padded weight copies ----------------
__global__ void k_padw(const float* __restrict__ wg1, const float* __restrict__ w1_rad) {
    int i = blockIdx.x * blockDim.x + threadIdx.x;
    if (i < KGIN * HIDN) g_wg1p[i] = (i < 273 * HIDN) ? wg1[i] : 0.0f;
    if (i < KWIN * HIDN) g_w1p[i]  = (i < 49 * HIDN)  ? w1_rad[i] : 0.0f;
}

// ---------------- k_prep: build padded input rows per active node ----------------
__global__ void __launch_bounds__(128)
k_prep(const float* __restrict__ h,
       const int*   __restrict__ z,
       const int*   __restrict__ absorber_index,
       const float* __restrict__ att_dist,
       const float* __restrict__ att_vec,
       const float* __restrict__ w_zemb)
{
    const int pos = blockIdx.x;
    if (pos >= g_count) return;
    const int tid = threadIdx.x;
    const int node = g_active[pos];
    const int b = node >> 7, n = node & 127;
    const int e = g_winner[node];
    const float d = att_dist[e];
    const int absb = absorber_index[b];
    const float isabs = (n == absb) ? 1.0f : 0.0f;
    const float width = CUTOFF_F / 15.0f;
    const float invwidth = 15.0f / CUTOFF_F;

    // win row (64, 49 used): [zemb 32 | isabs | rbf 16 | pad 15]
    if (tid < KWIN) {
        float v = 0.0f;
        if (tid < 32)       v = w_zemb[z[node] * 32 + tid];
        else if (tid == 32) v = isabs;
        else if (tid < 49) {
            float t = (d - (float)(tid - 33) * width) * invwidth;
            v = expf(-0.5f * t * t);
        }
        g_win[pos * KWIN + tid] = v;
    }
    // gin row (288, 273 used): [h_abs 128 | h 128 | rbf 16 | isabs | pad 15]
    g_gin[pos * KGIN + tid]       = h[(b * NN + absb) * H_DIM + tid];
    g_gin[pos * KGIN + 128 + tid] = h[node * H_DIM + tid];
    if (tid < 32) {
        float v = 0.0f;
        if (tid < 16) {
            float t = (d - (float)tid * width) * invwidth;
            v = expf(-0.5f * t * t);
        } else if (tid == 16) v = isabs;
        g_gin[pos * KGIN + 256 + tid] = v;
    }
    if (tid == 0)
        g_env[pos] = (d < CUTOFF_F) ? 0.5f * (cospif(d / CUTOFF_F) + 1.0f) : 0.0f;
    if (tid < 3)
        g_u[pos * 3 + tid] = att_vec[e * 3 + tid] / fmaxf(d, 1e-8f);
}

// ---------------- k_gate2: gate layer2 + sigmoid * env * norm ----------------
__global__ void __launch_bounds__(256)
k_gate2(const float* __restrict__ wg2, const float* __restrict__ bg2)
{
    int wid = threadIdx.x >> 5, lane = threadIdx.x & 31;
    int pos = blockIdx.x * 8 + wid;
    if (pos >= g_count) return;
    float s = 0.0f;
#pragma unroll
    for (int j = 0; j < 4; j++) {
        int k = lane + 32 * j;
        s += g_ghid[pos * HIDN + k] * wg2[k];
    }
#pragma unroll
    for (int off = 16; off > 0; off >>= 1) s += __shfl_xor_sync(0xffffffffu, s, off);
    if (lane == 0)
        g_mul[pos] = sigmoidf_(s + bg2[0]) * g_env[pos] * NORM_F;
}

// ---------------- small tiled SGEMM: 64x64x16, 256 thr, 4x4 ----------------
__global__ void __launch_bounds__(256)
k_gemm64(const float* __restrict__ A, const float* __restrict__ W,
         const float* __restrict__ bias, float* __restrict__ C,
         int M, int N, int K, int act)
{
    __shared__ __align__(16) float As[16][68];
    __shared__ __align__(16) float Ws[16][64];

    const int tid = threadIdx.x;
    const int tx = tid & 15, ty = tid >> 4;
    const int n0 = blockIdx.x * 64, m0 = blockIdx.y * 64;
    const int arow = tid >> 2, ac4 = tid & 3;
    const int wrow = tid >> 4, wc4 = tid & 15;

    float acc[4][4];
#pragma unroll
    for (int i = 0; i < 4; i++)
#pragma unroll
        for (int j = 0; j < 4; j++) acc[i][j] = 0.0f;

    for (int k0 = 0; k0 < K; k0 += 16) {
        float4 av = *reinterpret_cast<const float4*>(A + (size_t)(m0 + arow) * K + k0 + ac4 * 4);
        As[ac4 * 4 + 0][arow] = av.x;
        As[ac4 * 4 + 1][arow] = av.y;
        As[ac4 * 4 + 2][arow] = av.z;
        As[ac4 * 4 + 3][arow] = av.w;
        *reinterpret_cast<float4*>(&Ws[wrow][wc4 * 4]) =
            *reinterpret_cast<const float4*>(W + (size_t)(k0 + wrow) * N + n0 + wc4 * 4);
        __syncthreads();
#pragma unroll
        for (int k = 0; k < 16; k++) {
            float4 a = *reinterpret_cast<const float4*>(&As[k][ty * 4]);
            float4 b = *reinterpret_cast<const float4*>(&Ws[k][tx * 4]);
            float ar[4] = {a.x, a.y, a.z, a.w};
            float br[4] = {b.x, b.y, b.z, b.w};
#pragma unroll
            for (int i = 0; i < 4; i++)
#pragma unroll
                for (int j = 0; j < 4; j++) acc[i][j] += ar[i] * br[j];
        }
        __syncthreads();
    }

    float4 bb = *reinterpret_cast<const float4*>(bias + n0 + tx * 4);
    float bv[4] = {bb.x, bb.y, bb.z, bb.w};
#pragma unroll
    for (int i = 0; i < 4; i++) {
        float4 c;
        float cv[4];
#pragma unroll
        for (int j = 0; j < 4; j++) {
            float v = acc[i][j] + bv[j];
            if (act) v = siluf(v);
            cv[j] = v;
        }
        c.x = cv[0]; c.y = cv[1]; c.z = cv[2]; c.w = cv[3];
        *reinterpret_cast<float4*>(C + (size_t)(m0 + ty * 4 + i) * N + n0 + tx * 4) = c;
    }
}

// ---------------- big tiled SGEMM: 128x128x8, 256 thr, 8x8 ----------------
__global__ void __launch_bounds__(256, 2)
k_gemm128(const float* __restrict__ A, const float* __restrict__ W,
          const float* __restrict__ bias, float* __restrict__ C,
          int M, int N, int K, int act)
{
    __shared__ __align__(16) float As[8][132];
    __shared__ __align__(16) float Ws[8][128];

    const int tid = threadIdx.x;
    const int tx = tid & 15, ty = tid >> 4;
    const int n0 = blockIdx.x * 128, m0 = blockIdx.y * 128;
    const int arow = tid >> 1, aseg = tid & 1;
    const int wrow = tid >> 5, wc4 = tid & 31;

    float acc[8][8];
#pragma unroll
    for (int i = 0; i < 8; i++)
#pragma unroll
        for (int j = 0; j < 8; j++) acc[i][j] = 0.0f;

    for (int k0 = 0; k0 < K; k0 += 8) {
        float4 av = *reinterpret_cast<const float4*>(A + (size_t)(m0 + arow) * K + k0 + aseg * 4);
        As[aseg * 4 + 0][arow] = av.x;
        As[aseg * 4 + 1][arow] = av.y;
        As[aseg * 4 + 2][arow] = av.z;
        As[aseg * 4 + 3][arow] = av.w;
        *reinterpret_cast<float4*>(&Ws[wrow][wc4 * 4]) =
            *reinterpret_cast<const float4*>(W + (size_t)(k0 + wrow) * N + n0 + wc4 * 4);
        __syncthreads();
#pragma unroll
        for (int k = 0; k < 8; k++) {
            float4 a0 = *reinterpret_cast<const float4*>(&As[k][ty * 4]);
            float4 a1 = *reinterpret_cast<const float4*>(&As[k][64 + ty * 4]);
            float4 b0 = *reinterpret_cast<const float4*>(&Ws[k][tx * 4]);
            float4 b1 = *reinterpret_cast<const float4*>(&Ws[k][64 + tx * 4]);
            float ar[8] = {a0.x, a0.y, a0.z, a0.w, a1.x, a1.y, a1.z, a1.w};
            float br[8] = {b0.x, b0.y, b0.z, b0.w, b1.x, b1.y, b1.z, b1.w};
#pragma unroll
            for (int i = 0; i < 8; i++)
#pragma unroll
                for (int j = 0; j < 8; j++) acc[i][j] += ar[i] * br[j];
        }
        __syncthreads();
    }

    float4 bb0 = *reinterpret_cast<const float4*>(bias + n0 + tx * 4);
    float4 bb1 = *reinterpret_cast<const float4*>(bias + n0 + 64 + tx * 4);
    float bv[8] = {bb0.x, bb0.y, bb0.z, bb0.w, bb1.x, bb1.y, bb1.z, bb1.w};
#pragma unroll
    for (int i = 0; i < 8; i++) {
        int r = m0 + ((i < 4) ? (ty * 4 + i) : (64 + ty * 4 + i - 4));
        float cv[8];
#pragma unroll
        for (int j = 0; j < 8; j++) {
            float v = acc[i][j] + bv[j];
            if (act) v = siluf(v);
            cv[j] = v;
        }
        float4 c0 = {cv[0], cv[1], cv[2], cv[3]};
        float4 c1 = {cv[4], cv[5], cv[6], cv[7]};
        *reinterpret_cast<float4*>(C + (size_t)r * N + n0 + tx * 4) = c0;
        *reinterpret_cast<float4*>(C + (size_t)r * N + n0 + 64 + tx * 4) = c1;
    }
}

// ---------------- k_contract: tpw(4608) x node tensors -> ve(80) ----------------
__global__ void __launch_bounds__(128)
k_contract(const float* __restrict__ h_full)
{
    __shared__ float s1[NODE_S];
    __shared__ float v1s[NODE_V * 3];
    __shared__ float bvi[NODE_V];
    __shared__ float uu[3];

    const int pos = blockIdx.x;
    if (pos >= g_count) return;
    const int tid = threadIdx.x;
    const int node = g_active[pos];
    const float* hf = h_full + (size_t)node * 160;

    if (tid < NODE_S) s1[tid] = hf[tid];
    if (tid < NODE_V * 3) v1s[tid] = hf[NODE_S + tid];
    if (tid < 3) uu[tid] = g_u[pos * 3 + tid];
    __syncthreads();
    if (tid < NODE_V)
        bvi[tid] = v1s[3 * tid] * uu[0] + v1s[3 * tid + 1] * uu[1] + v1s[3 * tid + 2] * uu[2];
    __syncthreads();

    const float* tp = g_tpw + (size_t)pos * WN;
    const float mul = g_mul[pos];

    if (tid < OUT_S) {
        int o = tid;
        float acc = 0.0f;
#pragma unroll 8
        for (int i = 0; i < NODE_S; i++) acc += s1[i] * tp[i * OUT_S + o];
#pragma unroll 8
        for (int i = 0; i < NODE_V; i++) acc += bvi[i] * tp[2048 + i * OUT_S + o];
        g_ve[(size_t)node * OUT_DIM + o] = acc * mul;
    }
    if (tid >= 64 && tid < 112) {
        int t = tid - 64;
        int o = t & 15, c = t >> 4;      // o<16, c<3
        float sc = 0.0f, sd = 0.0f;
#pragma unroll 8
        for (int i = 0; i < NODE_S; i++) sc += s1[i] * tp[3072 + i * OUT_V + o];
#pragma unroll 8
        for (int i = 0; i < NODE_V; i++) sd += v1s[3 * i + c] * tp[4096 + i * OUT_V + o];
        float yv = SQRT3_F * uu[c];
        g_ve[(size_t)node * OUT_DIM + OUT_S + o * 3 + c] = (sc * yv + sd) * mul;
    }
}

// ---------------- k_vabs ----------------
__global__ void k_vabs() {
    int b = blockIdx.x, t = threadIdx.x;
    if (t >= OUT_DIM) return;
    float acc = 0.0f;
    for (int n = 0; n < NN; n++)
        acc += g_ve[(size_t)(b * NN + n) * OUT_DIM + t];
    g_vabs[b * OUT_DIM + t] = acc;
}

// ---------------- k_scales ----------------
__global__ void __launch_bounds__(128)
k_scales(const float* __restrict__ e_feat,
         const float* __restrict__ we1, const float* __restrict__ be1,
         const float* __restrict__ we2, const float* __restrict__ be2)
{
    __shared__ float hid[HIDN];
    int e = blockIdx.x, tid = threadIdx.x;
    float acc = be1[tid];
    for (int k = 0; k < 16; k++) acc += e_feat[e * 16 + k] * we1[k * HIDN + tid];
    hid[tid] = siluf(acc);
    __syncthreads();
    if (tid < 48) {
        float s = be2[tid];
        for (int k = 0; k < HIDN; k++) s += hid[k] * we2[k * 48 + tid];
        g_scales[e * 48 + tid] = s;
    }
}

// ---------------- k_inv ----------------
__global__ void __launch_bounds__(192)
k_inv()
{
    int row = blockIdx.x * 4 + threadIdx.x / 48;
    int j = threadIdx.x % 48;
    if (row >= ROWS3) return;
    int b = row >> 9, e = row & 511;
    float v;
    if (j < OUT_S) {
        v = g_vabs[b * OUT_DIM + j] * g_scales[e * 48 + j];
    } else {
        int o = j - OUT_S;
        float s = g_scales[e * 48 + OUT_S + o];
        float x0 = g_vabs[b * OUT_DIM + OUT_S + o * 3 + 0] * s;
        float x1 = g_vabs[b * OUT_DIM + OUT_S + o * 3 + 1] * s;
        float x2 = g_vabs[b * OUT_DIM + OUT_S + o * 3 + 2] * s;
        v = sqrtf(x0 * x0 + x1 * x1 + x2 * x2 + 1e-12f);
    }
    g_inv[(size_t)row * 48 + j] = v;
}

// ---------------- launch ----------------
extern "C" void kernel_launch(void* const* d_in, const int* in_sizes, int n_in,
                              void* d_out, int out_size)
{
    const float* h        = (const float*)d_in[0];
    const float* h_full   = (const float*)d_in[1];
    const int*   z        = (const int*)  d_in[2];
    const float* e_feat   = (const float*)d_in[4];
    const int*   abs_idx  = (const int*)  d_in[5];
    const int*   att_dst  = (const int*)  d_in[6];
    const float* att_dist = (const float*)d_in[7];
    const float* att_vec  = (const float*)d_in[8];
    const float* w_zemb   = (const float*)d_in[9];
    const float* w1_rad   = (const float*)d_in[10];
    const float* b1_rad   = (const float*)d_in[11];
    const float* w2_rad   = (const float*)d_in[12];
    const float* b2_rad   = (const float*)d_in[13];
    const float* wg1      = (const float*)d_in[14];
    const float* bg1      = (const float*)d_in[15];
    const float* wg2      = (const float*)d_in[16];
    const float* bg2      = (const float*)d_in[17];
    const float* we1      = (const float*)d_in[18];
    const float* be1      = (const float*)d_in[19];
    const float* we2      = (const float*)d_in[20];
    const float* be2      = (const float*)d_in[21];
    const float* wo1      = (const float*)d_in[22];
    const float* bo1      = (const float*)d_in[23];
    const float* wo2      = (const float*)d_in[24];
    const float* bo2      = (const float*)d_in[25];
    const float* wo3      = (const float*)d_in[26];
    const float* bo3      = (const float*)d_in[27];
    float* out = (float*)d_out;

    float *d_win, *d_gin, *d_ghid, *d_wg1p, *d_w1p, *d_hid, *d_tpw, *d_invp, *d_x1, *d_x2;
    cudaGetSymbolAddress((void**)&d_win,  g_win);
    cudaGetSymbolAddress((void**)&d_gin,  g_gin);
    cudaGetSymbolAddress((void**)&d_ghid, g_ghid);
    cudaGetSymbolAddress((void**)&d_wg1p, g_wg1p);
    cudaGetSymbolAddress((void**)&d_w1p,  g_w1p);
    cudaGetSymbolAddress((void**)&d_hid,  g_hid);
    cudaGetSymbolAddress((void**)&d_tpw,  g_tpw);
    cudaGetSymbolAddress((void**)&d_invp, g_inv);
    cudaGetSymbolAddress((void**)&d_x1,   g_x1);
    cudaGetSymbolAddress((void**)&d_x2,   g_x2);

    k_init<<<(FLAT * OUT_DIM + 255) / 256, 256>>>();
    k_scatter<<<(EATT_N + 255) / 256, 256>>>(att_dst);
    k_compact<<<(FLAT + 255) / 256, 256>>>();
    k_padw<<<(KGIN * HIDN + 255) / 256, 256>>>(wg1, w1_rad);
    k_prep<<<NACT_MAX, 128>>>(h, z, abs_idx, att_dist, att_vec, w_zemb);

    // gate hidden = silu(gin @ wg1p + bg1): 4096 x 128, K=288
    k_gemm64<<<dim3(2, NACT_MAX / 64), 256>>>(d_gin, d_wg1p, bg1, d_ghid, NACT_MAX, 128, KGIN, 1);
    // rad hidden = silu(win @ w1p + b1): 4096 x 128, K=64
    k_gemm64<<<dim3(2, NACT_MAX / 64), 256>>>(d_win, d_w1p, b1_rad, d_hid, NACT_MAX, 128, KWIN, 1);
    k_gate2<<<NACT_MAX / 8, 256>>>(wg2, bg2);

    // tpw = hid @ w2_rad + b2: 4096 x 4608, K=128
    k_gemm128<<<dim3(WN / 128, NACT_MAX / 128), 256>>>(d_hid, w2_rad, b2_rad, d_tpw, NACT_MAX, WN, HIDN, 0);
    k_contract<<<NACT_MAX, 128>>>(h_full);
    k_vabs<<<BB, 128>>>();
    k_scales<<<NEE, 128>>>(e_feat, we1, be1, we2, be2);
    k_inv<<<ROWS3 / 4, 192>>>();

    // tail MLP
    k_gemm128<<<dim3(1, ROWS3 / 128), 256>>>(d_invp, wo1, bo1, d_x1, ROWS3, 128, 48, 1);
    k_gemm128<<<dim3(1, ROWS3 / 128), 256>>>(d_x1, wo2, bo2, d_x2, ROWS3, 128, 128, 1);
    k_gemm128<<<dim3(2, ROWS3 / 128), 256>>>(d_x2, wo3, bo3, out, ROWS3, 256, 128, 0);
}